// round 12
// baseline (speedup 1.0000x reference)
#include <cuda_runtime.h>
#include <cuda_bf16.h>

// Problem constants
#define BB 4
#define PP 64
#define SS 8
#define YD 16
#define GD 48
#define NOUT (BB*PP*PP*SS*SS)          // 1,048,576 outputs

#define WARPS_PER_BLOCK 8              // 256 threads = 256 consecutive outputs

__device__ __forceinline__ float dot4(float4 v, float4 w) {
    return fmaf(v.x, w.x, fmaf(v.y, w.y, fmaf(v.z, w.z, v.w * w.w)));
}

// ---------------------------------------------------------------------------
// Fused kernel. Block = 256 consecutive outputs: (b,i) fixed, j spans 4
// values, (si,sj) full.
//
// Pipeline per block:
//   1. issue batch-1 g loads (6 coalesced LDG.128, 24 regs in flight)
//   2. lean prologue: tid<160 each compute ONE dot4 partial into pp[]
//      (entry e = tid>>2 of 40 = {sc1[4][8], sc2[8]}, quarter q = tid&3)
//   3. single __syncthreads (loads still in flight)
//   4. hot loop = proven R2 schedule (2x6 LDG.128, {A,B,C} register weight
//      columns, conflict-free STS.32 partials, 3x LDS.128 reduce)
//   5. epilogue: c1/c2 read straight from pp via one aligned LDS.128 each
//      (no stage-2 fold, no second barrier):
//        c1 = sum(pp[4*e1 .. 4*e1+3]),  e1 = jj*8 + sj
//        c2 = sum(pp[4*e2 .. 4*e2+3]),  e2 = 32 + si
//
// __launch_bounds__(256, 7): 36-reg ceiling — enough for 24 load regs + the
// lean prologue's ~8, guards against allocation drift below 7 blocks/SM.
// ---------------------------------------------------------------------------
__global__ __launch_bounds__(32 * WARPS_PER_BLOCK, 7)
void fused_kernel(const float* __restrict__ y,
                  const float* __restrict__ g,
                  const float* __restrict__ Wy,
                  const float* __restrict__ by,
                  const float* __restrict__ Wg,
                  const float* __restrict__ bg,
                  float* __restrict__ out) {
    __shared__ float part[WARPS_PER_BLOCK][12 * 32];
    __shared__ __align__(16) float pp[160];   // 40 entries x 4 quarters

    const int tid  = threadIdx.x;
    const int lane = tid & 31;
    const int wIn  = tid >> 5;
    const int blockBase = blockIdx.x * 256;

    // ---- 1. batch-1 loads first: 6 LDG.128 in flight ----
    const int base = blockBase + wIn * 32;
    const float4* gs = (const float4*)(g + (size_t)base * GD);
    float4 v0 = __ldcs(gs + lane +   0);
    float4 v1 = __ldcs(gs + lane +  32);
    float4 v2 = __ldcs(gs + lane +  64);
    float4 v3 = __ldcs(gs + lane +  96);
    float4 v4 = __ldcs(gs + lane + 128);
    float4 v5 = __ldcs(gs + lane + 160);

    // ---- 2. lean prologue: one dot4 per thread (tid < 160) ----
    if (tid < 160) {
        const int e = tid >> 2;                      // table entry 0..39
        const int q = tid & 3;                       // quarter of the 16-dot
        const int b  =  blockBase >> 18;
        const int i  = (blockBase >> 12) & 63;
        const int j0 = (blockBase >> 6)  & 63;       // low 2 bits are 0
        int row, woff;
        if (e < 32) { row = ((b << 6) + j0 + (e >> 3)) * SS + (e & 7); woff = 0; }
        else        { row = ((b << 6) + i) * SS + (e - 32);            woff = YD; }
        float4 yv = __ldg((const float4*)(y + (size_t)row * YD) + q);
        float4 wv = __ldg((const float4*)(Wy + woff) + q);
        pp[tid] = dot4(yv, wv);
    }

    // ---- 3. single barrier (g loads remain in flight) ----
    __syncthreads();

    // ---- per-lane weight columns: (lane%12 + {0,8,4}) % 12 ----
    const int l12 = lane % 12;
    int cB = l12 + 8; if (cB >= 12) cB -= 12;
    int cC = l12 + 4; if (cC >= 12) cC -= 12;
    const float4* wv = (const float4*)Wg;
    const float4 wA = __ldg(wv + l12);
    const float4 wB = __ldg(wv + cB);
    const float4 wC = __ldg(wv + cC);

    float* p = part[wIn];

    // ---- 4a. batch 1 compute ----
    p[lane +   0] = dot4(v0, wA);
    p[lane +  32] = dot4(v1, wB);
    p[lane +  64] = dot4(v2, wC);
    p[lane +  96] = dot4(v3, wA);
    p[lane + 128] = dot4(v4, wB);
    p[lane + 160] = dot4(v5, wC);

    // ---- 4b. batch 2 ----
    float4 u0 = __ldcs(gs + lane + 192);
    float4 u1 = __ldcs(gs + lane + 224);
    float4 u2 = __ldcs(gs + lane + 256);
    float4 u3 = __ldcs(gs + lane + 288);
    float4 u4 = __ldcs(gs + lane + 320);
    float4 u5 = __ldcs(gs + lane + 352);
    p[lane + 192] = dot4(u0, wA);
    p[lane + 224] = dot4(u1, wB);
    p[lane + 256] = dot4(u2, wC);
    p[lane + 288] = dot4(u3, wA);
    p[lane + 320] = dot4(u4, wB);
    p[lane + 352] = dot4(u5, wC);

    __syncwarp();

    // ---- reduce: lane r owns output base+r, partials at p[12r .. 12r+11] ----
    const float4* pr = (const float4*)(p + lane * 12);   // 48B aligned
    float4 t0 = pr[0], t1 = pr[1], t2 = pr[2];
    float sum = ((t0.x + t0.y) + (t0.z + t0.w))
              + ((t1.x + t1.y) + (t1.z + t1.w))
              + ((t2.x + t2.y) + (t2.z + t2.w));

    // ---- 5. epilogue: broadcast terms straight from pp ----
    // e1 = jj*8 + sj (jj = wIn>>1, sj = lane&7); e2 = 32 + si0 + (lane>>3)
    const float4 q1 = *((const float4*)pp + ((wIn >> 1) << 3) + (lane & 7));
    const float4 q2 = *((const float4*)pp + 32 + ((wIn & 1) << 2) + (lane >> 3));
    sum += ((q1.x + q1.y) + (q1.z + q1.w))
         + ((q2.x + q2.y) + (q2.z + q2.w))
         + __ldg(by) + __ldg(bg);

    __stcs(out + base + lane, sum);
}

// ---------------------------------------------------------------------------
// Launch
// inputs (metadata order): y(32768), pairwise_g(50331648), Wy(32), by(1),
//                          Wg(48), bg(1)
// ---------------------------------------------------------------------------
extern "C" void kernel_launch(void* const* d_in, const int* in_sizes, int n_in,
                              void* d_out, int out_size) {
    const float* y  = (const float*)d_in[0];
    const float* g  = (const float*)d_in[1];
    const float* Wy = (const float*)d_in[2];
    const float* by = (const float*)d_in[3];
    const float* Wg = (const float*)d_in[4];
    const float* bg = (const float*)d_in[5];
    float* out = (float*)d_out;

    const int blocks = NOUT / 256;                // 4096
    fused_kernel<<<blocks, 32 * WARPS_PER_BLOCK>>>(y, g, Wy, by, Wg, bg, out);
}

// round 13
// speedup vs baseline: 1.1298x; 1.1298x over previous
#include <cuda_runtime.h>
#include <cuda_bf16.h>

// Problem constants
#define BB 4
#define PP 64
#define SS 8
#define YD 16
#define GD 48
#define NOUT (BB*PP*PP*SS*SS)          // 1,048,576 outputs

#define WARPS_PER_BLOCK 8              // 256 threads = 256 consecutive outputs

__device__ __forceinline__ float dot4(float4 v, float4 w) {
    return fmaf(v.x, w.x, fmaf(v.y, w.y, fmaf(v.z, w.z, v.w * w.w)));
}

// ---------------------------------------------------------------------------
// Fused kernel. Block = 256 consecutive outputs: (b,i) fixed, j spans 4
// values, (si,sj) full.
//
// Prologue (strictly BEFORE any g load — twice-proven requirement):
//   tid<160: one dot4 quarter-partial per thread for table entry e=tid>>2
//   (40 entries = sc1[4][8], sc2[8]); entry quarters sit in one quad, so two
//   shfl_xor fold them in-warp and lane q==0 stores the finished entry.
//   ONE __syncthreads total.
//
// Hot loop (proven R2 schedule): per warp one 6KB g tile,
//   - 2 batches x 6 coalesced LDG.128 (lane l -> float4 f = l + 32k)
//   - weight column f%12 = (l%12+8k)%12 cycles {A,B,C}: 3 register float4s
//   - per-lane partial -> smem (conflict-free STS.32)
//   - lane r sums its 12 partials via 3 conflict-free LDS.128
//   - + sc1[jj][sj] + sc2[si] (broadcast LDS.32)
//
// __launch_bounds__(256, 7): 36-reg ceiling; safe because prologue regs are
// dead before the load batches (R11-proven).
// ---------------------------------------------------------------------------
__global__ __launch_bounds__(32 * WARPS_PER_BLOCK, 7)
void fused_kernel(const float* __restrict__ y,
                  const float* __restrict__ g,
                  const float* __restrict__ Wy,
                  const float* __restrict__ by,
                  const float* __restrict__ Wg,
                  const float* __restrict__ bg,
                  float* __restrict__ out) {
    __shared__ float part[WARPS_PER_BLOCK][12 * 32];
    __shared__ float sc1[4 * SS];      // c1[jj][s] (+bias)
    __shared__ float sc2[SS];          // c2[s]

    const int tid  = threadIdx.x;
    const int lane = tid & 31;
    const int wIn  = tid >> 5;
    const int blockBase = blockIdx.x * 256;

    // ---- prologue: one dot4 per thread, quad shuffle-fold, single store ----
    if (tid < 160) {
        const int e = tid >> 2;                      // table entry 0..39
        const int q = tid & 3;                       // quarter of the 16-dot
        const int b  =  blockBase >> 18;
        const int i  = (blockBase >> 12) & 63;
        const int j0 = (blockBase >> 6)  & 63;       // low 2 bits are 0
        int row, woff;
        if (e < 32) { row = ((b << 6) + j0 + (e >> 3)) * SS + (e & 7); woff = 0; }
        else        { row = ((b << 6) + i) * SS + (e - 32);            woff = YD; }
        float4 yv = __ldg((const float4*)(y + (size_t)row * YD) + q);
        float4 wv = __ldg((const float4*)(Wy + woff) + q);
        float d = dot4(yv, wv);
        d += __shfl_xor_sync(0xffffffffu, d, 1);
        d += __shfl_xor_sync(0xffffffffu, d, 2);
        if (q == 0) {
            if (e < 32) sc1[e] = d + __ldg(by) + __ldg(bg);
            else        sc2[e - 32] = d;
        }
    }
    __syncthreads();                    // prologue registers die here

    // ---- per-lane weight columns: (lane%12 + {0,8,4}) % 12 ----
    const int l12 = lane % 12;
    int cB = l12 + 8; if (cB >= 12) cB -= 12;
    int cC = l12 + 4; if (cC >= 12) cC -= 12;
    const float4* wv = (const float4*)Wg;
    const float4 wA = __ldg(wv + l12);
    const float4 wB = __ldg(wv + cB);
    const float4 wC = __ldg(wv + cC);

    const int base = blockBase + wIn * 32;
    const float4* gs = (const float4*)(g + (size_t)base * GD);
    float* p = part[wIn];

    // ---- batch 1: k = 0..5 (6 loads in flight) ----
    float4 v0 = __ldcs(gs + lane +   0);
    float4 v1 = __ldcs(gs + lane +  32);
    float4 v2 = __ldcs(gs + lane +  64);
    float4 v3 = __ldcs(gs + lane +  96);
    float4 v4 = __ldcs(gs + lane + 128);
    float4 v5 = __ldcs(gs + lane + 160);
    p[lane +   0] = dot4(v0, wA);
    p[lane +  32] = dot4(v1, wB);
    p[lane +  64] = dot4(v2, wC);
    p[lane +  96] = dot4(v3, wA);
    p[lane + 128] = dot4(v4, wB);
    p[lane + 160] = dot4(v5, wC);

    // ---- batch 2: k = 6..11 ----
    float4 u0 = __ldcs(gs + lane + 192);
    float4 u1 = __ldcs(gs + lane + 224);
    float4 u2 = __ldcs(gs + lane + 256);
    float4 u3 = __ldcs(gs + lane + 288);
    float4 u4 = __ldcs(gs + lane + 320);
    float4 u5 = __ldcs(gs + lane + 352);
    p[lane + 192] = dot4(u0, wA);
    p[lane + 224] = dot4(u1, wB);
    p[lane + 256] = dot4(u2, wC);
    p[lane + 288] = dot4(u3, wA);
    p[lane + 320] = dot4(u4, wB);
    p[lane + 352] = dot4(u5, wC);

    __syncwarp();

    // ---- reduce: lane r owns output base+r, partials at p[12r .. 12r+11] ----
    const float4* pr = (const float4*)(p + lane * 12);   // 48B aligned
    float4 t0 = pr[0], t1 = pr[1], t2 = pr[2];
    float sum = ((t0.x + t0.y) + (t0.z + t0.w))
              + ((t1.x + t1.y) + (t1.z + t1.w))
              + ((t2.x + t2.y) + (t2.z + t2.w));

    // broadcast terms: warp's jj = wIn>>1, si0 = (wIn&1)*4
    sum += sc1[((wIn >> 1) << 3) + (lane & 7)];
    sum += sc2[((wIn & 1) << 2) + (lane >> 3)];

    __stcs(out + base + lane, sum);
}

// ---------------------------------------------------------------------------
// Launch
// inputs (metadata order): y(32768), pairwise_g(50331648), Wy(32), by(1),
//                          Wg(48), bg(1)
// ---------------------------------------------------------------------------
extern "C" void kernel_launch(void* const* d_in, const int* in_sizes, int n_in,
                              void* d_out, int out_size) {
    const float* y  = (const float*)d_in[0];
    const float* g  = (const float*)d_in[1];
    const float* Wy = (const float*)d_in[2];
    const float* by = (const float*)d_in[3];
    const float* Wg = (const float*)d_in[4];
    const float* bg = (const float*)d_in[5];
    float* out = (float*)d_out;

    const int blocks = NOUT / 256;                // 4096
    fused_kernel<<<blocks, 32 * WARPS_PER_BLOCK>>>(y, g, Wy, by, Wg, bg, out);
}